// round 8
// baseline (speedup 1.0000x reference)
#include <cuda_runtime.h>
#include <cuda_fp16.h>
#include <math.h>

#define DIMC   128
#define HEADS  8
#define HD     16
#define DD     5
#define HH     24
#define WWID   48
#define NP     (DD*HH*WWID)   /* 5760 */
#define NH     576            /* padded halo rows (560 real) */
#define NREAL  560
#define RS2    72             /* attn KV row stride in halves (144B) */
#define GS2    72             /* gemm smem row stride in halves */

#define LOG2E      1.4426950408889634f
#define SHIFT2     5.7707801635558535f   /* 4*log2e */

typedef unsigned int u32;

// Scratch: split operands (hi/lo fp16), qkv fp16, attention out (hi/lo fp16)
__device__ __half g_xh[NP * DIMC],  g_xl[NP * DIMC];
__device__ __half g_wqh[384 * 128], g_wql[384 * 128];
__device__ __half g_wph[128 * 128], g_wpl[128 * 128];
__device__ __half g_qh[NP * DIMC];
__device__ __half g_kh[NP * DIMC];
__device__ __half g_vh[NP * DIMC];
__device__ __half g_ah[NP * DIMC],  g_al[NP * DIMC];

// ---------------------------------------------------------------------------
// helpers
// ---------------------------------------------------------------------------
__device__ __forceinline__ u32 smaddr(const void* p) { return (u32)__cvta_generic_to_shared(p); }

__device__ __forceinline__ void ldsm_x4(u32& r0, u32& r1, u32& r2, u32& r3, u32 a) {
    asm volatile("ldmatrix.sync.aligned.m8n8.x4.shared.b16 {%0,%1,%2,%3},[%4];"
                 : "=r"(r0), "=r"(r1), "=r"(r2), "=r"(r3) : "r"(a));
}
__device__ __forceinline__ void ldsm_x2(u32& r0, u32& r1, u32 a) {
    asm volatile("ldmatrix.sync.aligned.m8n8.x2.shared.b16 {%0,%1},[%2];"
                 : "=r"(r0), "=r"(r1) : "r"(a));
}
__device__ __forceinline__ void ldsm_x4_t(u32& r0, u32& r1, u32& r2, u32& r3, u32 a) {
    asm volatile("ldmatrix.sync.aligned.m8n8.x4.trans.shared.b16 {%0,%1,%2,%3},[%4];"
                 : "=r"(r0), "=r"(r1), "=r"(r2), "=r"(r3) : "r"(a));
}
__device__ __forceinline__ void ldsm_x2_t(u32& r0, u32& r1, u32 a) {
    asm volatile("ldmatrix.sync.aligned.m8n8.x2.trans.shared.b16 {%0,%1},[%2];"
                 : "=r"(r0), "=r"(r1) : "r"(a));
}
__device__ __forceinline__ void mma16816(float* d, u32 a0, u32 a1, u32 a2, u32 a3, u32 b0, u32 b1) {
    asm volatile("mma.sync.aligned.m16n8k16.row.col.f32.f16.f16.f32 "
                 "{%0,%1,%2,%3},{%4,%5,%6,%7},{%8,%9},{%0,%1,%2,%3};"
                 : "+f"(d[0]), "+f"(d[1]), "+f"(d[2]), "+f"(d[3])
                 : "r"(a0), "r"(a1), "r"(a2), "r"(a3), "r"(b0), "r"(b1));
}
__device__ __forceinline__ void mma1688(float* d, u32 a0, u32 a1, u32 b0) {
    asm volatile("mma.sync.aligned.m16n8k8.row.col.f32.f16.f16.f32 "
                 "{%0,%1,%2,%3},{%4,%5},{%6},{%0,%1,%2,%3};"
                 : "+f"(d[0]), "+f"(d[1]), "+f"(d[2]), "+f"(d[3])
                 : "r"(a0), "r"(a1), "r"(b0));
}
__device__ __forceinline__ u32 packh2(float x, float y) {
    __half2 h = __floats2half2_rn(x, y);
    return *(u32*)&h;
}
__device__ __forceinline__ float ex2(float x) {
    float r;
    asm("ex2.approx.f32 %0, %1;" : "=f"(r) : "f"(x));
    return r;
}
__device__ __forceinline__ void split2(float x, float y, u32& hi, u32& lo) {
    __half hx = __float2half_rn(x), hy = __float2half_rn(y);
    __half2 h2 = __halves2half2(hx, hy);
    hi = *(u32*)&h2;
    __half2 l2 = __floats2half2_rn(x - __half2float(hx), y - __half2float(hy));
    lo = *(u32*)&l2;
}

// ---------------------------------------------------------------------------
// Prep: split x / qkv_w / proj_w into hi/lo fp16 (once per launch)
// 200704 float4 total: [0,184320) x, [184320,196608) qkv_w, rest proj_w
// ---------------------------------------------------------------------------
__global__ __launch_bounds__(256) void split_prep(const float* __restrict__ x,
                                                  const float* __restrict__ wq,
                                                  const float* __restrict__ wp)
{
    int i = blockIdx.x * 256 + threadIdx.x;
    const float* src;
    __half *dh, *dl;
    int off;
    if (i < 184320)      { src = x;  dh = g_xh;  dl = g_xl;  off = i; }
    else if (i < 196608) { src = wq; dh = g_wqh; dl = g_wql; off = i - 184320; }
    else if (i < 200704) { src = wp; dh = g_wph; dl = g_wpl; off = i - 196608; }
    else return;
    float4 v = ((const float4*)src)[off];
    u32 h0, l0, h1, l1;
    split2(v.x, v.y, h0, l0);
    split2(v.z, v.w, h1, l1);
    *(uint2*)(dh + off * 4) = make_uint2(h0, h1);
    *(uint2*)(dl + off * 4) = make_uint2(l0, l1);
}

// ---------------------------------------------------------------------------
// Split-fp16 TC GEMM, pure fp16 inputs (pre-split), K in 2 chunks of 64.
// MODE 0: A=g_xh/xl, B=g_wqh/wql -> fp16 q(*0.25*log2e)/k/v
// MODE 1: A=g_ah/al, B=g_wph/wpl -> fp32 Cout (N=128)
// ---------------------------------------------------------------------------
struct SmemGemm {
    __half Ah[64 * GS2];
    __half Al[64 * GS2];
    __half Bh[64 * GS2];
    __half Bl[64 * GS2];
};

template<int MODE>
__global__ __launch_bounds__(256) void gemm_h(const __half* __restrict__ Agh,
                                              const __half* __restrict__ Agl,
                                              const __half* __restrict__ Bgh,
                                              const __half* __restrict__ Bgl,
                                              const float* __restrict__ bias,
                                              float* __restrict__ Cout)
{
    extern __shared__ char smraw[];
    SmemGemm* sm = (SmemGemm*)smraw;
    const int tid = threadIdx.x, warp = tid >> 5, lane = tid & 31;
    const int bm = blockIdx.x * 64, bn = blockIdx.y * 64;

    const int wm = warp >> 1, wn = warp & 1;
    const u32 aoff  = (u32)((wm * 16 + (lane & 15)) * GS2 + (lane >> 4) * 8) * 2;
    const u32 boff0 = (u32)((wn * 32 +      (lane & 15)) * GS2 + (lane >> 4) * 8) * 2;
    const u32 boff1 = (u32)((wn * 32 + 16 + (lane & 15)) * GS2 + (lane >> 4) * 8) * 2;
    const u32 ah_b  = smaddr(sm->Ah) + aoff;
    const u32 al_b  = smaddr(sm->Al) + aoff;
    const u32 bh_b0 = smaddr(sm->Bh) + boff0, bh_b1 = smaddr(sm->Bh) + boff1;
    const u32 bl_b0 = smaddr(sm->Bl) + boff0, bl_b1 = smaddr(sm->Bl) + boff1;

    float acc[4][4] = {};

    for (int k0 = 0; k0 < 128; k0 += 64) {
        if (k0) __syncthreads();
        // copy 64x64 fp16 tiles (2 uint4 per thread per array, no conversion)
#pragma unroll
        for (int t = 0; t < 2; t++) {
            int e = tid + t * 256;       // 0..511
            int row = e >> 3, c = e & 7; // row 0..63, 8-half group
            int gcol = k0 + c * 8;
            *(uint4*)(sm->Ah + row * GS2 + c * 8) = *(const uint4*)(Agh + (size_t)(bm + row) * 128 + gcol);
            *(uint4*)(sm->Al + row * GS2 + c * 8) = *(const uint4*)(Agl + (size_t)(bm + row) * 128 + gcol);
            *(uint4*)(sm->Bh + row * GS2 + c * 8) = *(const uint4*)(Bgh + (size_t)(bn + row) * 128 + gcol);
            *(uint4*)(sm->Bl + row * GS2 + c * 8) = *(const uint4*)(Bgl + (size_t)(bn + row) * 128 + gcol);
        }
        __syncthreads();

#pragma unroll
        for (int ks = 0; ks < 4; ks++) {
            const u32 kb = ks * 32;
            u32 ah0, ah1, ah2, ah3, al0, al1, al2, al3;
            ldsm_x4(ah0, ah1, ah2, ah3, ah_b + kb);
            ldsm_x4(al0, al1, al2, al3, al_b + kb);
            u32 b0, b1, b2, b3, b4, b5, b6, b7;
            ldsm_x4(b0, b1, b2, b3, bh_b0 + kb);
            ldsm_x4(b4, b5, b6, b7, bh_b1 + kb);
            mma16816(acc[0], ah0, ah1, ah2, ah3, b0, b2);
            mma16816(acc[1], ah0, ah1, ah2, ah3, b1, b3);
            mma16816(acc[2], ah0, ah1, ah2, ah3, b4, b6);
            mma16816(acc[3], ah0, ah1, ah2, ah3, b5, b7);
            mma16816(acc[0], al0, al1, al2, al3, b0, b2);
            mma16816(acc[1], al0, al1, al2, al3, b1, b3);
            mma16816(acc[2], al0, al1, al2, al3, b4, b6);
            mma16816(acc[3], al0, al1, al2, al3, b5, b7);
            ldsm_x4(b0, b1, b2, b3, bl_b0 + kb);
            ldsm_x4(b4, b5, b6, b7, bl_b1 + kb);
            mma16816(acc[0], ah0, ah1, ah2, ah3, b0, b2);
            mma16816(acc[1], ah0, ah1, ah2, ah3, b1, b3);
            mma16816(acc[2], ah0, ah1, ah2, ah3, b4, b6);
            mma16816(acc[3], ah0, ah1, ah2, ah3, b5, b7);
        }
    }

    // epilogue
    const int r0 = bm + wm * 16 + (lane >> 2);
    const int r1 = r0 + 8;
#pragma unroll
    for (int nt = 0; nt < 4; nt++) {
        const int cg = bn + wn * 32 + nt * 8 + 2 * (lane & 3);
        const float b0v = bias[cg], b1v = bias[cg + 1];
        float v00 = acc[nt][0] + b0v, v01 = acc[nt][1] + b1v;
        float v10 = acc[nt][2] + b0v, v11 = acc[nt][3] + b1v;
        if (MODE == 0) {
            const int seg = cg >> 7;       // 0=q,1=k,2=v (uniform per block)
            const int lc  = cg - seg * 128;
            __half* base = (seg == 0) ? g_qh : (seg == 1) ? g_kh : g_vh;
            if (seg == 0) {
                const float qs = 0.25f * LOG2E;
                v00 *= qs; v01 *= qs; v10 *= qs; v11 *= qs;
            }
            *(__half2*)(base + (size_t)r0 * DIMC + lc) = __floats2half2_rn(v00, v01);
            *(__half2*)(base + (size_t)r1 * DIMC + lc) = __floats2half2_rn(v10, v11);
        } else {
            *(float2*)(Cout + (size_t)r0 * 128 + cg) = make_float2(v00, v01);
            *(float2*)(Cout + (size_t)r1 * 128 + cg) = make_float2(v10, v11);
        }
    }
}

// ---------------------------------------------------------------------------
// Attention v3 (round-6 structure), epilogue writes hi/lo fp16 pairs.
// ---------------------------------------------------------------------------
struct SmemAttn {
    __half KV[NH * RS2];               // per row: [K h0 | K h1 | V h0 | V h1 | pad]
    __half Qs[10][16][24];
    int    rowmap[NH];
    unsigned short vmask[NH];
};

__global__ __launch_bounds__(320) void attn_mma(void)
{
    extern __shared__ char smraw[];
    SmemAttn* sm = (SmemAttn*)smraw;

    const int tid  = threadIdx.x;
    const int warp = tid >> 5;
    const int lane = tid & 31;

    const int hp   = blockIdx.x & 3;
    const int tile = blockIdx.x >> 2;
    const int tw   = tile % 6;
    const int th   = tile / 6;
    const int hy0  = th * 2;
    const int wx0  = tw * 8;

    const int hl   = warp / 5;
    const int dt   = warp % 5;
    const int head = hp * 2 + hl;

#pragma unroll
    for (int t = 0; t < 2; t++) {
        int rr = tid + t * 320;
        if (rr < NH) {
            int map = -1;
            unsigned vm = 0;
            if (rr < NREAL) {
                int d   = rr / 112;
                int rem = rr % 112;
                int ih  = rem / 14;
                int iw  = rem % 14;
                int h2  = (hy0 + ih + 21) % HH;
                int w2  = (wx0 + iw + 45) % WWID;
                map = (d * HH + h2) * WWID + w2;
                int wlo = iw - 6 < 0 ? 0 : iw - 6;
                int whi = iw < 7 ? iw : 7;
                unsigned wm = (whi >= wlo) ? ((0xFFu << wlo) & (0xFFu >> (7 - whi))) : 0u;
                unsigned m0 = (ih <= 6) ? wm : 0u;
                unsigned m1 = (ih >= 1) ? wm : 0u;
                vm = m0 | (m1 << 8);
            }
            sm->rowmap[rr] = map;
            sm->vmask[rr]  = (unsigned short)vm;
        }
    }
    {
        int r = lane >> 1, hf = lane & 1;
        int gp = ((dt * HH + hy0 + (r >> 3)) * WWID + wx0 + (r & 7));
        *(uint4*)&sm->Qs[warp][r][hf * 8] =
            *(const uint4*)(g_qh + (size_t)gp * DIMC + head * HD + hf * 8);
    }
    __syncthreads();

#pragma unroll
    for (int t = 0; t < 15; t++) {
        int e = tid + t * 320;
        if (e < NH * 8) {
            int row = e >> 3, c = e & 7;
            int cc  = c & 3;
            int g   = sm->rowmap[row];
            uint4 v = make_uint4(0u, 0u, 0u, 0u);
            const __half* base = (c < 4) ? g_kh : g_vh;
            if (g >= 0) v = *(const uint4*)(base + (size_t)g * DIMC + hp * 32 + cc * 8);
            *(uint4*)&sm->KV[row * RS2 + ((c < 4) ? 0 : 32) + cc * 8] = v;
        }
    }
    __syncthreads();

    const u32 qb  = smaddr(&sm->Qs[warp][0][0]);
    const u32 kvb = smaddr(sm->KV);
    const int r0  = lane >> 2;

    u32 qa0, qa1, qa2, qa3;
    {
        int l4 = lane & 15, cg = lane >> 4;
        ldsm_x4(qa0, qa1, qa2, qa3, qb + (u32)(l4 * 24 + cg * 8) * 2);
    }

    float dacc[8];
#pragma unroll
    for (int i = 0; i < 8; i++) dacc[i] = 0.f;
    float s0 = 0.f, s1 = 0.f;

#pragma unroll
    for (int ch = 0; ch < 8; ch++) {
        const int c0 = ch * 72;
        float c[9][4];
#pragma unroll
        for (int t = 0; t < 9; t++)
            c[t][0] = c[t][1] = c[t][2] = c[t][3] = -SHIFT2;

#pragma unroll
        for (int t = 0; t < 9; t++) {
            int l4 = lane & 15;
            u32 addr = kvb + (u32)((c0 + t * 8 + (l4 & 7)) * RS2 + hl * 16 + (l4 >> 3) * 8) * 2;
            u32 b0, b1;
            ldsm_x2(b0, b1, addr);
            mma16816(c[t], qa0, qa1, qa2, qa3, b0, b1);
        }

#pragma unroll
        for (int t = 0; t < 9; t++) {
            int cA = c0 + t * 8 + 2 * (lane & 3);
            u32 mm = *(const u32*)&sm->vmask[cA];
            float e0 = ex2(c[t][0]);
            float e1 = ex2(c[t][1]);
            float e2 = ex2(c[t][2]);
            float e3 = ex2(c[t][3]);
            e0 = ((mm >> (r0)) & 1u)      ? e0 : 0.f;
            e1 = ((mm >> (16 + r0)) & 1u) ? e1 : 0.f;
            e2 = ((mm >> (8 + r0)) & 1u)  ? e2 : 0.f;
            e3 = ((mm >> (24 + r0)) & 1u) ? e3 : 0.f;
            s0 += e0 + e1;
            s1 += e2 + e3;
            c[t][0] = e0; c[t][1] = e1; c[t][2] = e2; c[t][3] = e3;
        }

#pragma unroll
        for (int kc = 0; kc < 4; kc++) {
            u32 a0 = packh2(c[2 * kc][0], c[2 * kc][1]);
            u32 a1 = packh2(c[2 * kc][2], c[2 * kc][3]);
            u32 a2 = packh2(c[2 * kc + 1][0], c[2 * kc + 1][1]);
            u32 a3 = packh2(c[2 * kc + 1][2], c[2 * kc + 1][3]);
            int g = lane >> 3, rr2 = lane & 7;
            int row = c0 + kc * 16 + ((g & 1) << 3) + rr2;
            u32 addr = kvb + (u32)(row * RS2 + 32 + hl * 16 + (g >> 1) * 8) * 2;
            u32 b0, b1, b2, b3;
            ldsm_x4_t(b0, b1, b2, b3, addr);
            mma16816(dacc,     a0, a1, a2, a3, b0, b1);
            mma16816(dacc + 4, a0, a1, a2, a3, b2, b3);
        }
        {
            u32 a0 = packh2(c[8][0], c[8][1]);
            u32 a1 = packh2(c[8][2], c[8][3]);
            int l4 = lane & 15;
            int row = c0 + 64 + (l4 & 7);
            u32 addr = kvb + (u32)(row * RS2 + 32 + hl * 16 + (l4 >> 3) * 8) * 2;
            u32 b0, b1;
            ldsm_x2_t(b0, b1, addr);
            mma1688(dacc,     a0, a1, b0);
            mma1688(dacc + 4, a0, a1, b1);
        }
    }

    s0 += __shfl_xor_sync(0xFFFFFFFF, s0, 1);
    s0 += __shfl_xor_sync(0xFFFFFFFF, s0, 2);
    s1 += __shfl_xor_sync(0xFFFFFFFF, s1, 1);
    s1 += __shfl_xor_sync(0xFFFFFFFF, s1, 2);
    const float inv0 = 1.f / s0, inv1 = 1.f / s1;

    const int q4 = lane & 3;
    const int gp0 = ((dt * HH + hy0 + 0) * WWID + wx0 + r0);
    const int gp1 = ((dt * HH + hy0 + 1) * WWID + wx0 + r0);
    const size_t o0 = (size_t)gp0 * DIMC + head * HD;
    const size_t o1 = (size_t)gp1 * DIMC + head * HD;

    // write hi/lo split pairs (input for split-fp16 proj GEMM)
    {
        u32 hh, ll;
        float a, b;
        a = dacc[0] * inv0; b = dacc[1] * inv0;
        split2(a, b, hh, ll);
        *(u32*)(g_ah + o0 + 2 * q4) = hh;  *(u32*)(g_al + o0 + 2 * q4) = ll;
        a = dacc[2] * inv1; b = dacc[3] * inv1;
        split2(a, b, hh, ll);
        *(u32*)(g_ah + o1 + 2 * q4) = hh;  *(u32*)(g_al + o1 + 2 * q4) = ll;
        a = dacc[4] * inv0; b = dacc[5] * inv0;
        split2(a, b, hh, ll);
        *(u32*)(g_ah + o0 + 8 + 2 * q4) = hh;  *(u32*)(g_al + o0 + 8 + 2 * q4) = ll;
        a = dacc[6] * inv1; b = dacc[7] * inv1;
        split2(a, b, hh, ll);
        *(u32*)(g_ah + o1 + 8 + 2 * q4) = hh;  *(u32*)(g_al + o1 + 8 + 2 * q4) = ll;
    }
}

// ---------------------------------------------------------------------------
extern "C" void kernel_launch(void* const* d_in, const int* in_sizes, int n_in,
                              void* d_out, int out_size)
{
    const float* x      = (const float*)d_in[0];
    const float* qkv_w  = (const float*)d_in[1];
    const float* qkv_b  = (const float*)d_in[2];
    const float* proj_w = (const float*)d_in[3];
    const float* proj_b = (const float*)d_in[4];
    float* out = (float*)d_out;

    __half *xh, *xl, *wqh, *wql, *wph, *wpl, *ah, *al;
    cudaGetSymbolAddress((void**)&xh,  g_xh);
    cudaGetSymbolAddress((void**)&xl,  g_xl);
    cudaGetSymbolAddress((void**)&wqh, g_wqh);
    cudaGetSymbolAddress((void**)&wql, g_wql);
    cudaGetSymbolAddress((void**)&wph, g_wph);
    cudaGetSymbolAddress((void**)&wpl, g_wpl);
    cudaGetSymbolAddress((void**)&ah,  g_ah);
    cudaGetSymbolAddress((void**)&al,  g_al);

    static int attr_set = 0;
    if (!attr_set) {
        cudaFuncSetAttribute(attn_mma, cudaFuncAttributeMaxDynamicSharedMemorySize,
                             (int)sizeof(SmemAttn));
        cudaFuncSetAttribute(gemm_h<0>, cudaFuncAttributeMaxDynamicSharedMemorySize,
                             (int)sizeof(SmemGemm));
        cudaFuncSetAttribute(gemm_h<1>, cudaFuncAttributeMaxDynamicSharedMemorySize,
                             (int)sizeof(SmemGemm));
        attr_set = 1;
    }

    // 0) split x / weights into hi/lo fp16 (one memory-bound pass)
    split_prep<<<(200704 + 255) / 256, 256>>>(x, qkv_w, proj_w);
    // 1) QKV projection (pure fp16 split GEMM)
    gemm_h<0><<<dim3(NP / 64, 384 / 64), 256, sizeof(SmemGemm)>>>(xh, xl, wqh, wql, qkv_b, nullptr);
    // 2) attention (writes hi/lo)
    attn_mma<<<72 * 4, 320, sizeof(SmemAttn)>>>();
    // 3) output projection
    gemm_h<1><<<dim3(NP / 64, 128 / 64), 256, sizeof(SmemGemm)>>>(ah, al, wph, wpl, proj_b, out);
}

// round 9
// speedup vs baseline: 1.3916x; 1.3916x over previous
#include <cuda_runtime.h>
#include <cuda_fp16.h>
#include <math.h>

#define DIMC   128
#define HEADS  8
#define HD     16
#define DD     5
#define HH     24
#define WWID   48
#define NP     (DD*HH*WWID)   /* 5760 */
#define NH     576            /* padded halo rows (560 real) */
#define NREAL  560
#define RS2    72             /* attn KV row stride in halves (144B) */
#define GS2    72             /* gemm smem row stride in halves */

#define LOG2E      1.4426950408889634f
#define SHIFT2     5.7707801635558535f   /* 4*log2e */

typedef unsigned int u32;

// Scratch
__device__ __half g_qh[NP * DIMC];
__device__ __half g_kh[NP * DIMC];
__device__ __half g_vh[NP * DIMC];
__device__ float  g_att[NP * DIMC];

// ---------------------------------------------------------------------------
// helpers
// ---------------------------------------------------------------------------
__device__ __forceinline__ u32 smaddr(const void* p) { return (u32)__cvta_generic_to_shared(p); }

__device__ __forceinline__ void ldsm_x4(u32& r0, u32& r1, u32& r2, u32& r3, u32 a) {
    asm volatile("ldmatrix.sync.aligned.m8n8.x4.shared.b16 {%0,%1,%2,%3},[%4];"
                 : "=r"(r0), "=r"(r1), "=r"(r2), "=r"(r3) : "r"(a));
}
__device__ __forceinline__ void ldsm_x2(u32& r0, u32& r1, u32 a) {
    asm volatile("ldmatrix.sync.aligned.m8n8.x2.shared.b16 {%0,%1},[%2];"
                 : "=r"(r0), "=r"(r1) : "r"(a));
}
__device__ __forceinline__ void ldsm_x4_t(u32& r0, u32& r1, u32& r2, u32& r3, u32 a) {
    asm volatile("ldmatrix.sync.aligned.m8n8.x4.trans.shared.b16 {%0,%1,%2,%3},[%4];"
                 : "=r"(r0), "=r"(r1), "=r"(r2), "=r"(r3) : "r"(a));
}
__device__ __forceinline__ void ldsm_x2_t(u32& r0, u32& r1, u32 a) {
    asm volatile("ldmatrix.sync.aligned.m8n8.x2.trans.shared.b16 {%0,%1},[%2];"
                 : "=r"(r0), "=r"(r1) : "r"(a));
}
__device__ __forceinline__ void mma16816(float* d, u32 a0, u32 a1, u32 a2, u32 a3, u32 b0, u32 b1) {
    asm volatile("mma.sync.aligned.m16n8k16.row.col.f32.f16.f16.f32 "
                 "{%0,%1,%2,%3},{%4,%5,%6,%7},{%8,%9},{%0,%1,%2,%3};"
                 : "+f"(d[0]), "+f"(d[1]), "+f"(d[2]), "+f"(d[3])
                 : "r"(a0), "r"(a1), "r"(a2), "r"(a3), "r"(b0), "r"(b1));
}
__device__ __forceinline__ void mma1688(float* d, u32 a0, u32 a1, u32 b0) {
    asm volatile("mma.sync.aligned.m16n8k8.row.col.f32.f16.f16.f32 "
                 "{%0,%1,%2,%3},{%4,%5},{%6},{%0,%1,%2,%3};"
                 : "+f"(d[0]), "+f"(d[1]), "+f"(d[2]), "+f"(d[3])
                 : "r"(a0), "r"(a1), "r"(b0));
}
__device__ __forceinline__ u32 packh2(float x, float y) {
    __half2 h = __floats2half2_rn(x, y);
    return *(u32*)&h;
}
__device__ __forceinline__ float ex2(float x) {
    float r;
    asm("ex2.approx.f32 %0, %1;" : "=f"(r) : "f"(x));
    return r;
}
__device__ __forceinline__ void split2(float x, float y, u32& hi, u32& lo) {
    __half hx = __float2half_rn(x), hy = __float2half_rn(y);
    __half2 h2 = __halves2half2(hx, hy);
    hi = *(u32*)&h2;
    __half2 l2 = __floats2half2_rn(x - __half2float(hx), y - __half2float(hy));
    lo = *(u32*)&l2;
}

// ---------------------------------------------------------------------------
// Split-fp16 TC GEMM, K in 2 chunks of 64, regs capped for 4 CTAs/SM.
// Per k-step products ordered so al/bl fragments are register-transient:
//   ah*bh -> al*bh (al dies) -> ah*bl (bl reuses b regs)
// MODE 0: -> fp16 g_qh(*0.25*log2e)/g_kh/g_vh.  MODE 1: fp32 Cout (N=128).
// ---------------------------------------------------------------------------
struct SmemGemm {
    __half Ah[64 * GS2];
    __half Al[64 * GS2];
    __half Bh[64 * GS2];
    __half Bl[64 * GS2];
};

template<int MODE>
__global__ __launch_bounds__(256, 4) void gemm_tc(const float* __restrict__ A,
                                                  const float* __restrict__ Bm,
                                                  const float* __restrict__ bias,
                                                  float* __restrict__ Cout)
{
    extern __shared__ char smraw[];
    SmemGemm* sm = (SmemGemm*)smraw;
    const int tid = threadIdx.x, warp = tid >> 5, lane = tid & 31;
    const int bm = blockIdx.x * 64, bn = blockIdx.y * 64;

    const int wm = warp >> 1, wn = warp & 1;
    const u32 aoff  = (u32)((wm * 16 + (lane & 15)) * GS2 + (lane >> 4) * 8) * 2;
    const u32 boff0 = (u32)((wn * 32 +      (lane & 15)) * GS2 + (lane >> 4) * 8) * 2;
    const u32 boff1 = (u32)((wn * 32 + 16 + (lane & 15)) * GS2 + (lane >> 4) * 8) * 2;
    const u32 ah_b  = smaddr(sm->Ah) + aoff;
    const u32 al_b  = smaddr(sm->Al) + aoff;
    const u32 bh_b0 = smaddr(sm->Bh) + boff0, bh_b1 = smaddr(sm->Bh) + boff1;
    const u32 bl_b0 = smaddr(sm->Bl) + boff0, bl_b1 = smaddr(sm->Bl) + boff1;

    float acc[4][4] = {};

    for (int k0 = 0; k0 < 128; k0 += 64) {
        if (k0) __syncthreads();
        {   // load 64x64 fp32 chunk of A and B, split hi/lo fp16
            const int row = tid >> 2, q = tid & 3;
            const float* Ar = A  + (size_t)(bm + row) * 128 + k0 + q * 16;
            const float* Br = Bm + (size_t)(bn + row) * 128 + k0 + q * 16;
            __half* ah = sm->Ah + row * GS2 + q * 16;
            __half* al = sm->Al + row * GS2 + q * 16;
            __half* bh = sm->Bh + row * GS2 + q * 16;
            __half* bl = sm->Bl + row * GS2 + q * 16;
#pragma unroll
            for (int j = 0; j < 4; j++) {
                float4 v = *(const float4*)(Ar + j * 4);
                u32 h0, l0, h1, l1;
                split2(v.x, v.y, h0, l0);
                split2(v.z, v.w, h1, l1);
                *(uint2*)(ah + j * 4) = make_uint2(h0, h1);
                *(uint2*)(al + j * 4) = make_uint2(l0, l1);
                float4 w = *(const float4*)(Br + j * 4);
                split2(w.x, w.y, h0, l0);
                split2(w.z, w.w, h1, l1);
                *(uint2*)(bh + j * 4) = make_uint2(h0, h1);
                *(uint2*)(bl + j * 4) = make_uint2(l0, l1);
            }
        }
        __syncthreads();

#pragma unroll
        for (int ks = 0; ks < 4; ks++) {
            const u32 kb = ks * 32;
            u32 ah0, ah1, ah2, ah3;
            u32 b0, b1, b2, b3, b4, b5, b6, b7;
            // hi * hi
            ldsm_x4(ah0, ah1, ah2, ah3, ah_b + kb);
            ldsm_x4(b0, b1, b2, b3, bh_b0 + kb);
            ldsm_x4(b4, b5, b6, b7, bh_b1 + kb);
            mma16816(acc[0], ah0, ah1, ah2, ah3, b0, b2);
            mma16816(acc[1], ah0, ah1, ah2, ah3, b1, b3);
            mma16816(acc[2], ah0, ah1, ah2, ah3, b4, b6);
            mma16816(acc[3], ah0, ah1, ah2, ah3, b5, b7);
            // lo(A) * hi(B): al transient
            {
                u32 al0, al1, al2, al3;
                ldsm_x4(al0, al1, al2, al3, al_b + kb);
                mma16816(acc[0], al0, al1, al2, al3, b0, b2);
                mma16816(acc[1], al0, al1, al2, al3, b1, b3);
                mma16816(acc[2], al0, al1, al2, al3, b4, b6);
                mma16816(acc[3], al0, al1, al2, al3, b5, b7);
            }
            // hi(A) * lo(B): bl reuses b regs
            ldsm_x4(b0, b1, b2, b3, bl_b0 + kb);
            ldsm_x4(b4, b5, b6, b7, bl_b1 + kb);
            mma16816(acc[0], ah0, ah1, ah2, ah3, b0, b2);
            mma16816(acc[1], ah0, ah1, ah2, ah3, b1, b3);
            mma16816(acc[2], ah0, ah1, ah2, ah3, b4, b6);
            mma16816(acc[3], ah0, ah1, ah2, ah3, b5, b7);
        }
    }

    // epilogue
    const int r0 = bm + wm * 16 + (lane >> 2);
    const int r1 = r0 + 8;
#pragma unroll
    for (int nt = 0; nt < 4; nt++) {
        const int cg = bn + wn * 32 + nt * 8 + 2 * (lane & 3);
        const float b0v = bias[cg], b1v = bias[cg + 1];
        float v00 = acc[nt][0] + b0v, v01 = acc[nt][1] + b1v;
        float v10 = acc[nt][2] + b0v, v11 = acc[nt][3] + b1v;
        if (MODE == 0) {
            const int seg = cg >> 7;
            const int lc  = cg - seg * 128;
            __half* base = (seg == 0) ? g_qh : (seg == 1) ? g_kh : g_vh;
            if (seg == 0) {
                const float qs = 0.25f * LOG2E;
                v00 *= qs; v01 *= qs; v10 *= qs; v11 *= qs;
            }
            *(__half2*)(base + (size_t)r0 * DIMC + lc) = __floats2half2_rn(v00, v01);
            *(__half2*)(base + (size_t)r1 * DIMC + lc) = __floats2half2_rn(v10, v11);
        } else {
            *(float2*)(Cout + (size_t)r0 * 128 + cg) = make_float2(v00, v01);
            *(float2*)(Cout + (size_t)r1 * 128 + cg) = make_float2(v10, v11);
        }
    }
}

// ---------------------------------------------------------------------------
// Attention v3 (round-6 exact): block = (2x8 hw tile) x 5 depths x 2 heads.
// ---------------------------------------------------------------------------
struct SmemAttn {
    __half KV[NH * RS2];               // per row: [K h0 | K h1 | V h0 | V h1 | pad]
    __half Qs[10][16][24];
    int    rowmap[NH];
    unsigned short vmask[NH];
};

__global__ __launch_bounds__(320) void attn_mma(void)
{
    extern __shared__ char smraw[];
    SmemAttn* sm = (SmemAttn*)smraw;

    const int tid  = threadIdx.x;
    const int warp = tid >> 5;
    const int lane = tid & 31;

    const int hp   = blockIdx.x & 3;
    const int tile = blockIdx.x >> 2;
    const int tw   = tile % 6;
    const int th   = tile / 6;
    const int hy0  = th * 2;
    const int wx0  = tw * 8;

    const int hl   = warp / 5;
    const int dt   = warp % 5;
    const int head = hp * 2 + hl;

#pragma unroll
    for (int t = 0; t < 2; t++) {
        int rr = tid + t * 320;
        if (rr < NH) {
            int map = -1;
            unsigned vm = 0;
            if (rr < NREAL) {
                int d   = rr / 112;
                int rem = rr % 112;
                int ih  = rem / 14;
                int iw  = rem % 14;
                int h2  = (hy0 + ih + 21) % HH;
                int w2  = (wx0 + iw + 45) % WWID;
                map = (d * HH + h2) * WWID + w2;
                int wlo = iw - 6 < 0 ? 0 : iw - 6;
                int whi = iw < 7 ? iw : 7;
                unsigned wm = (whi >= wlo) ? ((0xFFu << wlo) & (0xFFu >> (7 - whi))) : 0u;
                unsigned m0 = (ih <= 6) ? wm : 0u;
                unsigned m1 = (ih >= 1) ? wm : 0u;
                vm = m0 | (m1 << 8);
            }
            sm->rowmap[rr] = map;
            sm->vmask[rr]  = (unsigned short)vm;
        }
    }
    {
        int r = lane >> 1, hf = lane & 1;
        int gp = ((dt * HH + hy0 + (r >> 3)) * WWID + wx0 + (r & 7));
        *(uint4*)&sm->Qs[warp][r][hf * 8] =
            *(const uint4*)(g_qh + (size_t)gp * DIMC + head * HD + hf * 8);
    }
    __syncthreads();

#pragma unroll
    for (int t = 0; t < 15; t++) {
        int e = tid + t * 320;
        if (e < NH * 8) {
            int row = e >> 3, c = e & 7;
            int cc  = c & 3;
            int g   = sm->rowmap[row];
            uint4 v = make_uint4(0u, 0u, 0u, 0u);
            const __half* base = (c < 4) ? g_kh : g_vh;
            if (g >= 0) v = *(const uint4*)(base + (size_t)g * DIMC + hp * 32 + cc * 8);
            *(uint4*)&sm->KV[row * RS2 + ((c < 4) ? 0 : 32) + cc * 8] = v;
        }
    }
    __syncthreads();

    const u32 qb  = smaddr(&sm->Qs[warp][0][0]);
    const u32 kvb = smaddr(sm->KV);
    const int r0  = lane >> 2;

    u32 qa0, qa1, qa2, qa3;
    {
        int l4 = lane & 15, cg = lane >> 4;
        ldsm_x4(qa0, qa1, qa2, qa3, qb + (u32)(l4 * 24 + cg * 8) * 2);
    }

    float dacc[8];
#pragma unroll
    for (int i = 0; i < 8; i++) dacc[i] = 0.f;
    float s0 = 0.f, s1 = 0.f;

#pragma unroll
    for (int ch = 0; ch < 8; ch++) {
        const int c0 = ch * 72;
        float c[9][4];
#pragma unroll
        for (int t = 0; t < 9; t++)
            c[t][0] = c[t][1] = c[t][2] = c[t][3] = -SHIFT2;

#pragma unroll
        for (int t = 0; t < 9; t++) {
            int l4 = lane & 15;
            u32 addr = kvb + (u32)((c0 + t * 8 + (l4 & 7)) * RS2 + hl * 16 + (l4 >> 3) * 8) * 2;
            u32 b0, b1;
            ldsm_x2(b0, b1, addr);
            mma16816(c[t], qa0, qa1, qa2, qa3, b0, b1);
        }

#pragma unroll
        for (int t = 0; t < 9; t++) {
            int cA = c0 + t * 8 + 2 * (lane & 3);
            u32 mm = *(const u32*)&sm->vmask[cA];
            float e0 = ex2(c[t][0]);
            float e1 = ex2(c[t][1]);
            float e2 = ex2(c[t][2]);
            float e3 = ex2(c[t][3]);
            e0 = ((mm >> (r0)) & 1u)      ? e0 : 0.f;
            e1 = ((mm >> (16 + r0)) & 1u) ? e1 : 0.f;
            e2 = ((mm >> (8 + r0)) & 1u)  ? e2 : 0.f;
            e3 = ((mm >> (24 + r0)) & 1u) ? e3 : 0.f;
            s0 += e0 + e1;
            s1 += e2 + e3;
            c[t][0] = e0; c[t][1] = e1; c[t][2] = e2; c[t][3] = e3;
        }

#pragma unroll
        for (int kc = 0; kc < 4; kc++) {
            u32 a0 = packh2(c[2 * kc][0], c[2 * kc][1]);
            u32 a1 = packh2(c[2 * kc][2], c[2 * kc][3]);
            u32 a2 = packh2(c[2 * kc + 1][0], c[2 * kc + 1][1]);
            u32 a3 = packh2(c[2 * kc + 1][2], c[2 * kc + 1][3]);
            int g = lane >> 3, rr2 = lane & 7;
            int row = c0 + kc * 16 + ((g & 1) << 3) + rr2;
            u32 addr = kvb + (u32)(row * RS2 + 32 + hl * 16 + (g >> 1) * 8) * 2;
            u32 b0, b1, b2, b3;
            ldsm_x4_t(b0, b1, b2, b3, addr);
            mma16816(dacc,     a0, a1, a2, a3, b0, b1);
            mma16816(dacc + 4, a0, a1, a2, a3, b2, b3);
        }
        {
            u32 a0 = packh2(c[8][0], c[8][1]);
            u32 a1 = packh2(c[8][2], c[8][3]);
            int l4 = lane & 15;
            int row = c0 + 64 + (l4 & 7);
            u32 addr = kvb + (u32)(row * RS2 + 32 + hl * 16 + (l4 >> 3) * 8) * 2;
            u32 b0, b1;
            ldsm_x2_t(b0, b1, addr);
            mma1688(dacc,     a0, a1, b0);
            mma1688(dacc + 4, a0, a1, b1);
        }
    }

    s0 += __shfl_xor_sync(0xFFFFFFFF, s0, 1);
    s0 += __shfl_xor_sync(0xFFFFFFFF, s0, 2);
    s1 += __shfl_xor_sync(0xFFFFFFFF, s1, 1);
    s1 += __shfl_xor_sync(0xFFFFFFFF, s1, 2);
    const float inv0 = 1.f / s0, inv1 = 1.f / s1;

    const int q4 = lane & 3;
    const int gp0 = ((dt * HH + hy0 + 0) * WWID + wx0 + r0);
    const int gp1 = ((dt * HH + hy0 + 1) * WWID + wx0 + r0);
    float* o0 = g_att + (size_t)gp0 * DIMC + head * HD;
    float* o1 = g_att + (size_t)gp1 * DIMC + head * HD;
    *(float2*)(o0 + 2 * q4)     = make_float2(dacc[0] * inv0, dacc[1] * inv0);
    *(float2*)(o1 + 2 * q4)     = make_float2(dacc[2] * inv1, dacc[3] * inv1);
    *(float2*)(o0 + 8 + 2 * q4) = make_float2(dacc[4] * inv0, dacc[5] * inv0);
    *(float2*)(o1 + 8 + 2 * q4) = make_float2(dacc[6] * inv1, dacc[7] * inv1);
}

// ---------------------------------------------------------------------------
extern "C" void kernel_launch(void* const* d_in, const int* in_sizes, int n_in,
                              void* d_out, int out_size)
{
    const float* x      = (const float*)d_in[0];
    const float* qkv_w  = (const float*)d_in[1];
    const float* qkv_b  = (const float*)d_in[2];
    const float* proj_w = (const float*)d_in[3];
    const float* proj_b = (const float*)d_in[4];
    float* out = (float*)d_out;

    float* att;
    cudaGetSymbolAddress((void**)&att, g_att);

    static int attr_set = 0;
    if (!attr_set) {
        cudaFuncSetAttribute(attn_mma, cudaFuncAttributeMaxDynamicSharedMemorySize,
                             (int)sizeof(SmemAttn));
        cudaFuncSetAttribute(gemm_tc<0>, cudaFuncAttributeMaxDynamicSharedMemorySize,
                             (int)sizeof(SmemGemm));
        cudaFuncSetAttribute(gemm_tc<1>, cudaFuncAttributeMaxDynamicSharedMemorySize,
                             (int)sizeof(SmemGemm));
        attr_set = 1;
    }

    // QKV projection (split-fp16 TC) -> fp16 q(*0.25*log2e)/k/v
    gemm_tc<0><<<dim3(NP / 64, 384 / 64), 256, sizeof(SmemGemm)>>>(x, qkv_w, qkv_b, nullptr);
    // Neighborhood attention (d-fused, warp-local softmax)
    attn_mma<<<72 * 4, 320, sizeof(SmemAttn)>>>();
    // Output projection (split-fp16 TC) -> fp32 out
    gemm_tc<1><<<dim3(NP / 64, 128 / 64), 256, sizeof(SmemGemm)>>>(att, proj_w, proj_b, out);
}

// round 10
// speedup vs baseline: 1.4723x; 1.0580x over previous
#include <cuda_runtime.h>
#include <cuda_fp16.h>
#include <math.h>

#define DIMC   128
#define HEADS  8
#define HD     16
#define DD     5
#define HH     24
#define WWID   48
#define NP     (DD*HH*WWID)   /* 5760 */
#define NH     576            /* padded halo rows (560 real) */
#define NREAL  560
#define RS2    72             /* attn KV row stride in halves (144B) */
#define GS2    72             /* gemm smem row stride in halves */

#define LOG2E      1.4426950408889634f
#define SHIFT2     5.7707801635558535f   /* 4*log2e */

typedef unsigned int u32;

// Scratch
__device__ __half g_xh[NP * DIMC],  g_xl[NP * DIMC];
__device__ __half g_wqh[384 * 128], g_wql[384 * 128];
__device__ __half g_wph[128 * 128], g_wpl[128 * 128];
__device__ __half g_qh[NP * DIMC];
__device__ __half g_kh[NP * DIMC];
__device__ __half g_vh[NP * DIMC];
__device__ float  g_att[NP * DIMC];

// ---------------------------------------------------------------------------
// helpers
// ---------------------------------------------------------------------------
__device__ __forceinline__ u32 smaddr(const void* p) { return (u32)__cvta_generic_to_shared(p); }

__device__ __forceinline__ void ldsm_x4(u32& r0, u32& r1, u32& r2, u32& r3, u32 a) {
    asm volatile("ldmatrix.sync.aligned.m8n8.x4.shared.b16 {%0,%1,%2,%3},[%4];"
                 : "=r"(r0), "=r"(r1), "=r"(r2), "=r"(r3) : "r"(a));
}
__device__ __forceinline__ void ldsm_x2(u32& r0, u32& r1, u32 a) {
    asm volatile("ldmatrix.sync.aligned.m8n8.x2.shared.b16 {%0,%1},[%2];"
                 : "=r"(r0), "=r"(r1) : "r"(a));
}
__device__ __forceinline__ void ldsm_x4_t(u32& r0, u32& r1, u32& r2, u32& r3, u32 a) {
    asm volatile("ldmatrix.sync.aligned.m8n8.x4.trans.shared.b16 {%0,%1,%2,%3},[%4];"
                 : "=r"(r0), "=r"(r1), "=r"(r2), "=r"(r3) : "r"(a));
}
__device__ __forceinline__ void ldsm_x2_t(u32& r0, u32& r1, u32 a) {
    asm volatile("ldmatrix.sync.aligned.m8n8.x2.trans.shared.b16 {%0,%1},[%2];"
                 : "=r"(r0), "=r"(r1) : "r"(a));
}
__device__ __forceinline__ void mma16816(float* d, u32 a0, u32 a1, u32 a2, u32 a3, u32 b0, u32 b1) {
    asm volatile("mma.sync.aligned.m16n8k16.row.col.f32.f16.f16.f32 "
                 "{%0,%1,%2,%3},{%4,%5,%6,%7},{%8,%9},{%0,%1,%2,%3};"
                 : "+f"(d[0]), "+f"(d[1]), "+f"(d[2]), "+f"(d[3])
                 : "r"(a0), "r"(a1), "r"(a2), "r"(a3), "r"(b0), "r"(b1));
}
__device__ __forceinline__ void mma1688(float* d, u32 a0, u32 a1, u32 b0) {
    asm volatile("mma.sync.aligned.m16n8k8.row.col.f32.f16.f16.f32 "
                 "{%0,%1,%2,%3},{%4,%5},{%6},{%0,%1,%2,%3};"
                 : "+f"(d[0]), "+f"(d[1]), "+f"(d[2]), "+f"(d[3])
                 : "r"(a0), "r"(a1), "r"(b0));
}
__device__ __forceinline__ u32 packh2(float x, float y) {
    __half2 h = __floats2half2_rn(x, y);
    return *(u32*)&h;
}
__device__ __forceinline__ float ex2(float x) {
    float r;
    asm("ex2.approx.f32 %0, %1;" : "=f"(r) : "f"(x));
    return r;
}
__device__ __forceinline__ void split2(float x, float y, u32& hi, u32& lo) {
    __half hx = __float2half_rn(x), hy = __float2half_rn(y);
    __half2 h2 = __halves2half2(hx, hy);
    hi = *(u32*)&h2;
    __half2 l2 = __floats2half2_rn(x - __half2float(hx), y - __half2float(hy));
    lo = *(u32*)&l2;
}

// ---------------------------------------------------------------------------
// Prep: split x / qkv_w / proj_w into hi/lo fp16, once.
// 200704 float4: [0,184320) x, [184320,196608) qkv_w, rest proj_w
// ---------------------------------------------------------------------------
__global__ __launch_bounds__(256) void split_prep(const float* __restrict__ x,
                                                  const float* __restrict__ wq,
                                                  const float* __restrict__ wp)
{
    int i = blockIdx.x * 256 + threadIdx.x;
    const float* src;
    __half *dh, *dl;
    int off;
    if (i < 184320)      { src = x;  dh = g_xh;  dl = g_xl;  off = i; }
    else if (i < 196608) { src = wq; dh = g_wqh; dl = g_wql; off = i - 184320; }
    else if (i < 200704) { src = wp; dh = g_wph; dl = g_wpl; off = i - 196608; }
    else return;
    float4 v = ((const float4*)src)[off];
    u32 h0, l0, h1, l1;
    split2(v.x, v.y, h0, l0);
    split2(v.z, v.w, h1, l1);
    *(uint2*)(dh + off * 4) = make_uint2(h0, h1);
    *(uint2*)(dl + off * 4) = make_uint2(l0, l1);
}

// ---------------------------------------------------------------------------
// GEMM shared pieces (64x64 tile, K in 2 chunks of 64, 8 warps 16x32 each)
// ---------------------------------------------------------------------------
struct SmemGemm {
    __half Ah[64 * GS2];
    __half Al[64 * GS2];
    __half Bh[64 * GS2];
    __half Bl[64 * GS2];
};

__device__ __forceinline__ void gemm_mainchunk(SmemGemm* sm, float acc[4][4],
                                               u32 ah_b, u32 al_b,
                                               u32 bh_b0, u32 bh_b1,
                                               u32 bl_b0, u32 bl_b1)
{
#pragma unroll
    for (int ks = 0; ks < 4; ks++) {
        const u32 kb = ks * 32;
        u32 ah0, ah1, ah2, ah3;
        u32 b0, b1, b2, b3, b4, b5, b6, b7;
        ldsm_x4(ah0, ah1, ah2, ah3, ah_b + kb);
        ldsm_x4(b0, b1, b2, b3, bh_b0 + kb);
        ldsm_x4(b4, b5, b6, b7, bh_b1 + kb);
        mma16816(acc[0], ah0, ah1, ah2, ah3, b0, b2);
        mma16816(acc[1], ah0, ah1, ah2, ah3, b1, b3);
        mma16816(acc[2], ah0, ah1, ah2, ah3, b4, b6);
        mma16816(acc[3], ah0, ah1, ah2, ah3, b5, b7);
        {
            u32 al0, al1, al2, al3;
            ldsm_x4(al0, al1, al2, al3, al_b + kb);
            mma16816(acc[0], al0, al1, al2, al3, b0, b2);
            mma16816(acc[1], al0, al1, al2, al3, b1, b3);
            mma16816(acc[2], al0, al1, al2, al3, b4, b6);
            mma16816(acc[3], al0, al1, al2, al3, b5, b7);
        }
        ldsm_x4(b0, b1, b2, b3, bl_b0 + kb);
        ldsm_x4(b4, b5, b6, b7, bl_b1 + kb);
        mma16816(acc[0], ah0, ah1, ah2, ah3, b0, b2);
        mma16816(acc[1], ah0, ah1, ah2, ah3, b1, b3);
        mma16816(acc[2], ah0, ah1, ah2, ah3, b4, b6);
        mma16816(acc[3], ah0, ah1, ah2, ah3, b5, b7);
    }
}

// QKV GEMM: all operands pre-split fp16. Epilogue -> g_qh(*0.25*log2e)/g_kh/g_vh.
__global__ __launch_bounds__(256, 4) void gemm_qkv(const float* __restrict__ bias)
{
    extern __shared__ char smraw[];
    SmemGemm* sm = (SmemGemm*)smraw;
    const int tid = threadIdx.x, warp = tid >> 5, lane = tid & 31;
    const int bm = blockIdx.x * 64, bn = blockIdx.y * 64;

    const int wm = warp >> 1, wn = warp & 1;
    const u32 aoff  = (u32)((wm * 16 + (lane & 15)) * GS2 + (lane >> 4) * 8) * 2;
    const u32 boff0 = (u32)((wn * 32 +      (lane & 15)) * GS2 + (lane >> 4) * 8) * 2;
    const u32 boff1 = (u32)((wn * 32 + 16 + (lane & 15)) * GS2 + (lane >> 4) * 8) * 2;
    const u32 ah_b  = smaddr(sm->Ah) + aoff;
    const u32 al_b  = smaddr(sm->Al) + aoff;
    const u32 bh_b0 = smaddr(sm->Bh) + boff0, bh_b1 = smaddr(sm->Bh) + boff1;
    const u32 bl_b0 = smaddr(sm->Bl) + boff0, bl_b1 = smaddr(sm->Bl) + boff1;

    float acc[4][4] = {};

    for (int k0 = 0; k0 < 128; k0 += 64) {
        if (k0) __syncthreads();
#pragma unroll
        for (int t = 0; t < 2; t++) {
            int e = tid + t * 256;
            int row = e >> 3, c = e & 7;
            int gcol = k0 + c * 8;
            *(uint4*)(sm->Ah + row * GS2 + c * 8) = *(const uint4*)(g_xh  + (size_t)(bm + row) * 128 + gcol);
            *(uint4*)(sm->Al + row * GS2 + c * 8) = *(const uint4*)(g_xl  + (size_t)(bm + row) * 128 + gcol);
            *(uint4*)(sm->Bh + row * GS2 + c * 8) = *(const uint4*)(g_wqh + (size_t)(bn + row) * 128 + gcol);
            *(uint4*)(sm->Bl + row * GS2 + c * 8) = *(const uint4*)(g_wql + (size_t)(bn + row) * 128 + gcol);
        }
        __syncthreads();
        gemm_mainchunk(sm, acc, ah_b, al_b, bh_b0, bh_b1, bl_b0, bl_b1);
    }

    const int r0 = bm + wm * 16 + (lane >> 2);
    const int r1 = r0 + 8;
#pragma unroll
    for (int nt = 0; nt < 4; nt++) {
        const int cg = bn + wn * 32 + nt * 8 + 2 * (lane & 3);
        const float b0v = bias[cg], b1v = bias[cg + 1];
        float v00 = acc[nt][0] + b0v, v01 = acc[nt][1] + b1v;
        float v10 = acc[nt][2] + b0v, v11 = acc[nt][3] + b1v;
        const int seg = cg >> 7;       // 0=q,1=k,2=v (uniform per block)
        const int lc  = cg - seg * 128;
        __half* base = (seg == 0) ? g_qh : (seg == 1) ? g_kh : g_vh;
        if (seg == 0) {
            const float qs = 0.25f * LOG2E;
            v00 *= qs; v01 *= qs; v10 *= qs; v11 *= qs;
        }
        *(__half2*)(base + (size_t)r0 * DIMC + lc) = __floats2half2_rn(v00, v01);
        *(__half2*)(base + (size_t)r1 * DIMC + lc) = __floats2half2_rn(v10, v11);
    }
}

// Proj GEMM: A = g_att fp32 (split in-block), B pre-split. -> fp32 out.
__global__ __launch_bounds__(256, 4) void gemm_proj(const float* __restrict__ A,
                                                    const float* __restrict__ bias,
                                                    float* __restrict__ Cout)
{
    extern __shared__ char smraw[];
    SmemGemm* sm = (SmemGemm*)smraw;
    const int tid = threadIdx.x, warp = tid >> 5, lane = tid & 31;
    const int bm = blockIdx.x * 64, bn = blockIdx.y * 64;

    const int wm = warp >> 1, wn = warp & 1;
    const u32 aoff  = (u32)((wm * 16 + (lane & 15)) * GS2 + (lane >> 4) * 8) * 2;
    const u32 boff0 = (u32)((wn * 32 +      (lane & 15)) * GS2 + (lane >> 4) * 8) * 2;
    const u32 boff1 = (u32)((wn * 32 + 16 + (lane & 15)) * GS2 + (lane >> 4) * 8) * 2;
    const u32 ah_b  = smaddr(sm->Ah) + aoff;
    const u32 al_b  = smaddr(sm->Al) + aoff;
    const u32 bh_b0 = smaddr(sm->Bh) + boff0, bh_b1 = smaddr(sm->Bh) + boff1;
    const u32 bl_b0 = smaddr(sm->Bl) + boff0, bl_b1 = smaddr(sm->Bl) + boff1;

    float acc[4][4] = {};

    for (int k0 = 0; k0 < 128; k0 += 64) {
        if (k0) __syncthreads();
        {   // A: fp32 -> split in-block; B: pre-split copy
            const int row = tid >> 2, q = tid & 3;
            const float* Ar = A + (size_t)(bm + row) * 128 + k0 + q * 16;
            __half* ah = sm->Ah + row * GS2 + q * 16;
            __half* al = sm->Al + row * GS2 + q * 16;
#pragma unroll
            for (int j = 0; j < 4; j++) {
                float4 v = *(const float4*)(Ar + j * 4);
                u32 h0, l0, h1, l1;
                split2(v.x, v.y, h0, l0);
                split2(v.z, v.w, h1, l1);
                *(uint2*)(ah + j * 4) = make_uint2(h0, h1);
                *(uint2*)(al + j * 4) = make_uint2(l0, l1);
            }
#pragma unroll
            for (int t = 0; t < 2; t++) {
                int e = tid + t * 256;
                int rowb = e >> 3, c = e & 7;
                int gcol = k0 + c * 8;
                *(uint4*)(sm->Bh + rowb * GS2 + c * 8) = *(const uint4*)(g_wph + (size_t)(bn + rowb) * 128 + gcol);
                *(uint4*)(sm->Bl + rowb * GS2 + c * 8) = *(const uint4*)(g_wpl + (size_t)(bn + rowb) * 128 + gcol);
            }
        }
        __syncthreads();
        gemm_mainchunk(sm, acc, ah_b, al_b, bh_b0, bh_b1, bl_b0, bl_b1);
    }

    const int r0 = bm + wm * 16 + (lane >> 2);
    const int r1 = r0 + 8;
#pragma unroll
    for (int nt = 0; nt < 4; nt++) {
        const int cg = bn + wn * 32 + nt * 8 + 2 * (lane & 3);
        const float b0v = bias[cg], b1v = bias[cg + 1];
        *(float2*)(Cout + (size_t)r0 * 128 + cg) = make_float2(acc[nt][0] + b0v, acc[nt][1] + b1v);
        *(float2*)(Cout + (size_t)r1 * 128 + cg) = make_float2(acc[nt][2] + b0v, acc[nt][3] + b1v);
    }
}

// ---------------------------------------------------------------------------
// Attention (identical to round 9 winner)
// ---------------------------------------------------------------------------
struct SmemAttn {
    __half KV[NH * RS2];
    __half Qs[10][16][24];
    int    rowmap[NH];
    unsigned short vmask[NH];
};

__global__ __launch_bounds__(320) void attn_mma(void)
{
    extern __shared__ char smraw[];
    SmemAttn* sm = (SmemAttn*)smraw;

    const int tid  = threadIdx.x;
    const int warp = tid >> 5;
    const int lane = tid & 31;

    const int hp   = blockIdx.x & 3;
    const int tile = blockIdx.x >> 2;
    const int tw   = tile % 6;
    const int th   = tile / 6;
    const int hy0  = th * 2;
    const int wx0  = tw * 8;

    const int hl   = warp / 5;
    const int dt   = warp % 5;
    const int head = hp * 2 + hl;

#pragma unroll
    for (int t = 0; t < 2; t++) {
        int rr = tid + t * 320;
        if (rr < NH) {
            int map = -1;
            unsigned vm = 0;
            if (rr < NREAL) {
                int d   = rr / 112;
                int rem = rr % 112;
                int ih  = rem / 14;
                int iw  = rem % 14;
                int h2  = (hy0 + ih + 21) % HH;
                int w2  = (wx0 + iw + 45) % WWID;
                map = (d * HH + h2) * WWID + w2;
                int wlo = iw - 6 < 0 ? 0 : iw - 6;
                int whi = iw < 7 ? iw : 7;
                unsigned wm = (whi >= wlo) ? ((0xFFu << wlo) & (0xFFu >> (7 - whi))) : 0u;
                unsigned m0 = (ih <= 6) ? wm : 0u;
                unsigned m1 = (ih >= 1) ? wm : 0u;
                vm = m0 | (m1 << 8);
            }
            sm->rowmap[rr] = map;
            sm->vmask[rr]  = (unsigned short)vm;
        }
    }
    {
        int r = lane >> 1, hf = lane & 1;
        int gp = ((dt * HH + hy0 + (r >> 3)) * WWID + wx0 + (r & 7));
        *(uint4*)&sm->Qs[warp][r][hf * 8] =
            *(const uint4*)(g_qh + (size_t)gp * DIMC + head * HD + hf * 8);
    }
    __syncthreads();

#pragma unroll
    for (int t = 0; t < 15; t++) {
        int e = tid + t * 320;
        if (e < NH * 8) {
            int row = e >> 3, c = e & 7;
            int cc  = c & 3;
            int g   = sm->rowmap[row];
            uint4 v = make_uint4(0u, 0u, 0u, 0u);
            const __half* base = (c < 4) ? g_kh : g_vh;
            if (g >= 0) v = *(const uint4*)(base + (size_t)g * DIMC + hp * 32 + cc * 8);
            *(uint4*)&sm->KV[row * RS2 + ((c < 4) ? 0 : 32) + cc * 8] = v;
        }
    }
    __syncthreads();

    const u32 qb  = smaddr(&sm->Qs[warp][0][0]);
    const u32 kvb = smaddr(sm->KV);
    const int r0  = lane >> 2;

    u32 qa0, qa1, qa2, qa3;
    {
        int l4 = lane & 15, cg = lane >> 4;
        ldsm_x4(qa0, qa1, qa2, qa3, qb + (u32)(l4 * 24 + cg * 8) * 2);
    }

    float dacc[8];
#pragma unroll
    for (int i = 0; i < 8; i++) dacc[i] = 0.f;
    float s0 = 0.f, s1 = 0.f;

#pragma unroll
    for (int ch = 0; ch < 8; ch++) {
        const int c0 = ch * 72;
        float c[9][4];
#pragma unroll
        for (int t = 0; t < 9; t++)
            c[t][0] = c[t][1] = c[t][2] = c[t][3] = -SHIFT2;

#pragma unroll
        for (int t = 0; t < 9; t++) {
            int l4 = lane & 15;
            u32 addr = kvb + (u32)((c0 + t * 8 + (l4 & 7)) * RS2 + hl * 16 + (l4 >> 3) * 8) * 2;
            u32 b0, b1;
            ldsm_x2(b0, b1, addr);
            mma16816(c[t], qa0, qa1, qa2, qa3, b0, b1);
        }

#pragma unroll
        for (int t = 0; t < 9; t++) {
            int cA = c0 + t * 8 + 2 * (lane & 3);
            u32 mm = *(const u32*)&sm->vmask[cA];
            float e0 = ex2(c[t][0]);
            float e1 = ex2(c[t][1]);
            float e2 = ex2(c[t][2]);
            float e3 = ex2(c[t][3]);
            e0 = ((mm >> (r0)) & 1u)      ? e0 : 0.f;
            e1 = ((mm >> (16 + r0)) & 1u) ? e1 : 0.f;
            e2 = ((mm >> (8 + r0)) & 1u)  ? e2 : 0.f;
            e3 = ((mm >> (24 + r0)) & 1u) ? e3 : 0.f;
            s0 += e0 + e1;
            s1 += e2 + e3;
            c[t][0] = e0; c[t][1] = e1; c[t][2] = e2; c[t][3] = e3;
        }

#pragma unroll
        for (int kc = 0; kc < 4; kc++) {
            u32 a0 = packh2(c[2 * kc][0], c[2 * kc][1]);
            u32 a1 = packh2(c[2 * kc][2], c[2 * kc][3]);
            u32 a2 = packh2(c[2 * kc + 1][0], c[2 * kc + 1][1]);
            u32 a3 = packh2(c[2 * kc + 1][2], c[2 * kc + 1][3]);
            int g = lane >> 3, rr2 = lane & 7;
            int row = c0 + kc * 16 + ((g & 1) << 3) + rr2;
            u32 addr = kvb + (u32)(row * RS2 + 32 + hl * 16 + (g >> 1) * 8) * 2;
            u32 b0, b1, b2, b3;
            ldsm_x4_t(b0, b1, b2, b3, addr);
            mma16816(dacc,     a0, a1, a2, a3, b0, b1);
            mma16816(dacc + 4, a0, a1, a2, a3, b2, b3);
        }
        {
            u32 a0 = packh2(c[8][0], c[8][1]);
            u32 a1 = packh2(c[8][2], c[8][3]);
            int l4 = lane & 15;
            int row = c0 + 64 + (l4 & 7);
            u32 addr = kvb + (u32)(row * RS2 + 32 + hl * 16 + (l4 >> 3) * 8) * 2;
            u32 b0, b1;
            ldsm_x2_t(b0, b1, addr);
            mma1688(dacc,     a0, a1, b0);
            mma1688(dacc + 4, a0, a1, b1);
        }
    }

    s0 += __shfl_xor_sync(0xFFFFFFFF, s0, 1);
    s0 += __shfl_xor_sync(0xFFFFFFFF, s0, 2);
    s1 += __shfl_xor_sync(0xFFFFFFFF, s1, 1);
    s1 += __shfl_xor_sync(0xFFFFFFFF, s1, 2);
    const float inv0 = 1.f / s0, inv1 = 1.f / s1;

    const int q4 = lane & 3;
    const int gp0 = ((dt * HH + hy0 + 0) * WWID + wx0 + r0);
    const int gp1 = ((dt * HH + hy0 + 1) * WWID + wx0 + r0);
    float* o0 = g_att + (size_t)gp0 * DIMC + head * HD;
    float* o1 = g_att + (size_t)gp1 * DIMC + head * HD;
    *(float2*)(o0 + 2 * q4)     = make_float2(dacc[0] * inv0, dacc[1] * inv0);
    *(float2*)(o1 + 2 * q4)     = make_float2(dacc[2] * inv1, dacc[3] * inv1);
    *(float2*)(o0 + 8 + 2 * q4) = make_float2(dacc[4] * inv0, dacc[5] * inv0);
    *(float2*)(o1 + 8 + 2 * q4) = make_float2(dacc[6] * inv1, dacc[7] * inv1);
}

// ---------------------------------------------------------------------------
extern "C" void kernel_launch(void* const* d_in, const int* in_sizes, int n_in,
                              void* d_out, int out_size)
{
    const float* x      = (const float*)d_in[0];
    const float* qkv_w  = (const float*)d_in[1];
    const float* qkv_b  = (const float*)d_in[2];
    const float* proj_w = (const float*)d_in[3];
    const float* proj_b = (const float*)d_in[4];
    float* out = (float*)d_out;

    float* att;
    cudaGetSymbolAddress((void**)&att, g_att);

    static int attr_set = 0;
    if (!attr_set) {
        cudaFuncSetAttribute(attn_mma, cudaFuncAttributeMaxDynamicSharedMemorySize,
                             (int)sizeof(SmemAttn));
        cudaFuncSetAttribute(gemm_qkv, cudaFuncAttributeMaxDynamicSharedMemorySize,
                             (int)sizeof(SmemGemm));
        cudaFuncSetAttribute(gemm_proj, cudaFuncAttributeMaxDynamicSharedMemorySize,
                             (int)sizeof(SmemGemm));
        attr_set = 1;
    }

    // 0) one-shot hi/lo split of x and weights
    split_prep<<<(200704 + 255) / 256, 256>>>(x, qkv_w, proj_w);
    // 1) QKV projection (all-presplit fp16 TC GEMM)
    gemm_qkv<<<dim3(NP / 64, 384 / 64), 256, sizeof(SmemGemm)>>>(qkv_b);
    // 2) neighborhood attention (unchanged)
    attn_mma<<<72 * 4, 320, sizeof(SmemAttn)>>>();
    // 3) output projection (B presplit, A split in-block)
    gemm_proj<<<dim3(NP / 64, 128 / 64), 256, sizeof(SmemGemm)>>>(att, proj_b, out);
}